// round 8
// baseline (speedup 1.0000x reference)
#include <cuda_runtime.h>
#include <math.h>

#define BB 4
#define CIN 64
#define COUT 64
#define HH 128
#define WW 128
#define KK 9
#define HW (HH*WW)

#define FMA2(d, a, b, c) asm("fma.rn.f32x2 %0, %1, %2, %3;" : "=l"(d) : "l"(a), "l"(b), "l"(c))
#define PACK2(d, lo, hi) asm("mov.b64 %0, {%1, %2};" : "=l"(d) : "f"(lo), "f"(hi))
#define UNPACK2(lo, hi, d) asm("mov.b64 {%0, %1}, %2;" : "=f"(lo), "=f"(hi) : "l"(d))

// ------------- device scratch (static, no allocation) -------------
__device__ float g_off[BB*10*HW];        // conv1 output, channels 0..9
__device__ float g_stats1[BB*5*2];       // GN1 sum/sumsq for groups 0..4
__device__ float g_xT[BB*HW*CIN];        // x transposed to [b][h][w][ci]
__device__ float g_wT[KK*CIN*COUT];      // w_dsc transposed to [k][ci][co]
__device__ float g_outraw[BB*COUT*HW];   // conv2 output before GN2
__device__ float g_stats2[BB*16*2];      // GN2 sum/sumsq

// ------------- prep: zero stats, transpose w_dsc -------------
__global__ void prep_kernel(const float* __restrict__ w_dsc) {
    int idx = blockIdx.x*256 + threadIdx.x;
    if (idx < KK*CIN*COUT) {
        int k  = idx / (CIN*COUT);
        int r  = idx % (CIN*COUT);
        int ci = r / COUT;
        int co = r % COUT;
        g_wT[idx] = w_dsc[(co*CIN + ci)*KK + k];
    }
    if (idx < BB*5*2)  g_stats1[idx] = 0.f;
    if (idx < BB*16*2) g_stats2[idx] = 0.f;
}

// ------------- conv1: 3x3 SAME, ch 0..9, f32x2 over channel pairs ----
// block (64,2)=128 thr, each thread 1 px x 10 ch. grid (2, 64, 4).
__global__ __launch_bounds__(128) void conv1_kernel(
        const float* __restrict__ x,
        const float* __restrict__ w_off,
        const float* __restrict__ b_off) {
    __shared__ float sw2[576*12];    // [(ci*9+tap)][c] rows padded to 12
    __shared__ float s_sum[5], s_sq[5];
    int tid = threadIdx.y*64 + threadIdx.x;
    for (int i = tid; i < 5760; i += 128) {
        int c = i / 576;
        int r = i % 576;          // ci*9 + tap
        sw2[r*12 + c] = w_off[i];
    }
    if (tid < 5) { s_sum[tid] = 0.f; s_sq[tid] = 0.f; }
    __syncthreads();

    int b = blockIdx.z;
    int h = blockIdx.y*2 + threadIdx.y;
    int w = blockIdx.x*64 + threadIdx.x;

    unsigned long long acc2[5];
    #pragma unroll
    for (int c2 = 0; c2 < 5; c2++)
        PACK2(acc2[c2], b_off[c2*2], b_off[c2*2+1]);

    bool vm = (w > 0), vp = (w < 127);
    const float* xb = x + (size_t)b*CIN*HW;

    for (int ci = 0; ci < CIN; ci++) {
        const float* xc = xb + ci*HW;
        #pragma unroll
        for (int dy = -1; dy <= 1; dy++) {
            int hy = h + dy;
            bool rv = (hy >= 0) && (hy < HH);
            const float* row = xc + hy*WW + w;
            float x0 = (rv && vm) ? row[-1] : 0.f;
            float x1 = rv         ? row[0]  : 0.f;
            float x2 = (rv && vp) ? row[1]  : 0.f;
            unsigned long long xd[3];
            PACK2(xd[0], x0, x0);
            PACK2(xd[1], x1, x1);
            PACK2(xd[2], x2, x2);
            const float* wbase = &sw2[(ci*9 + (dy+1)*3)*12];
            #pragma unroll
            for (int tap = 0; tap < 3; tap++) {
                const float* wrow = wbase + tap*12;
                const ulonglong2 wa = *(const ulonglong2*)wrow;
                const ulonglong2 wb = *(const ulonglong2*)(wrow+4);
                const unsigned long long wc = *(const unsigned long long*)(wrow+8);
                FMA2(acc2[0], wa.x, xd[tap], acc2[0]);
                FMA2(acc2[1], wa.y, xd[tap], acc2[1]);
                FMA2(acc2[2], wb.x, xd[tap], acc2[2]);
                FMA2(acc2[3], wb.y, xd[tap], acc2[3]);
                FMA2(acc2[4], wc,   xd[tap], acc2[4]);
            }
        }
    }

    float ps[5], pq[5];
    #pragma unroll
    for (int c2 = 0; c2 < 5; c2++) {
        float v0, v1;
        UNPACK2(v0, v1, acc2[c2]);
        g_off[((b*10 + 2*c2    )*HH + h)*WW + w] = v0;
        g_off[((b*10 + 2*c2 + 1)*HH + h)*WW + w] = v1;
        ps[c2] = v0 + v1;
        pq[c2] = v0*v0 + v1*v1;
    }
    #pragma unroll
    for (int g = 0; g < 5; g++) {
        atomicAdd(&s_sum[g], ps[g]);
        atomicAdd(&s_sq[g],  pq[g]);
    }
    __syncthreads();
    if (tid < 5) {
        atomicAdd(&g_stats1[(b*5+tid)*2+0], s_sum[tid]);
        atomicAdd(&g_stats1[(b*5+tid)*2+1], s_sq[tid]);
    }
}

// ------------- transpose x: [b][ci][s] -> [b][s][ci] -------------
__global__ __launch_bounds__(256) void transpose_kernel(const float* __restrict__ x) {
    __shared__ float tile[32][33];
    int b  = blockIdx.z;
    int s0 = blockIdx.x*32;
    int c0 = blockIdx.y*32;
    #pragma unroll
    for (int r = 0; r < 4; r++) {
        int ci = c0 + threadIdx.y + r*8;
        tile[threadIdx.y + r*8][threadIdx.x] =
            x[((size_t)b*CIN + ci)*HW + s0 + threadIdx.x];
    }
    __syncthreads();
    #pragma unroll
    for (int r = 0; r < 4; r++) {
        int s = s0 + threadIdx.y + r*8;
        g_xT[((size_t)b*HW + s)*CIN + c0 + threadIdx.x] = tile[threadIdx.x][threadIdx.y + r*8];
    }
}

// ------------- fused: GN1+tanh+cumsum -> sample -> f32x2 GEMM -> stats2 ----
// grid (128, 4): (h, b); 256 threads; dynamic smem.
// Block tile: 64 co x 128 px (one h row). Thread tile: 4 co x 8 px.
// smem (floats):
#define SM_W    0        // w_dup[ci][co] duplicated pairs: 64*64*2 = 8192
#define SM_V    8192     // v[ci][px]: 64*128 = 8192
#define SM_Y0   16384    // int y0[9][128] = 1152
#define SM_WY   17536    // float wy[9][128] = 1152
#define SM_RED  16384    // aliased over coords (used after last build)
#define SM_FLOATS 18688  // 74752 bytes

__global__ __launch_bounds__(256, 3) void fused_kernel(
        const float* __restrict__ g_gn_off,
        const float* __restrict__ b_gn_off,
        const float* __restrict__ b_dsc) {
    extern __shared__ float smf[];
    int* smi = (int*)smf;

    int t = threadIdx.x;
    int b = blockIdx.y;
    int h = blockIdx.x;

    // --- setup: threads 0..127 compute per-pixel offsets -> smem coords ---
    if (t < 128) {
        int w = t;
        float tv[9];
        #pragma unroll
        for (int c = 0; c < 9; c++) {
            int g = c >> 1;
            float s = g_stats1[(b*5 + g)*2 + 0];
            float q = g_stats1[(b*5 + g)*2 + 1];
            float mean = s * (1.f/32768.f);
            float var  = q * (1.f/32768.f) - mean*mean;
            float inv  = rsqrtf(var + 1e-5f);
            float v = g_off[((b*10 + c)*HH + h)*WW + w];
            tv[c] = tanhf((v - mean)*inv*g_gn_off[c] + b_gn_off[c]);
        }
        float yoff[9];
        yoff[4] = 0.f;
        yoff[3] = tv[3];
        yoff[2] = yoff[3] + tv[2];
        yoff[1] = yoff[2] + tv[1];
        yoff[0] = yoff[1] + tv[0];
        yoff[5] = tv[5];
        yoff[6] = yoff[5] + tv[6];
        yoff[7] = yoff[6] + tv[7];
        yoff[8] = yoff[7] + tv[8];
        #pragma unroll
        for (int k = 0; k < 9; k++) {
            float yc = (float)h + yoff[k];
            yc = fminf(fmaxf(yc, 0.f), 127.f);
            int y0 = (int)floorf(yc);
            y0 = min(max(y0, 0), 127);
            smi[SM_Y0 + k*128 + w] = y0;
            smf[SM_WY + k*128 + w] = yc - (float)y0;
        }
    }
    __syncthreads();

    int co0 = (t & 15) * 4;    // 4 output channels
    int p0  = (t >> 4) * 8;    // 8 pixels (4 f32x2 pairs)
    int px   = t & 127;        // build: pixel
    int half = t >> 7;         // build: ci half (0..31 / 32..63)

    unsigned long long acc[4][4];
    #pragma unroll
    for (int i = 0; i < 4; i++)
        #pragma unroll
        for (int j = 0; j < 4; j++) acc[i][j] = 0ULL;

    const float* xTb = g_xT + (size_t)b*HW*CIN;

    for (int k = 0; k < 9; k++) {
        if (k) __syncthreads();
        // load + duplicate weight slice [ci][co] -> (w,w) pairs
        {
            const float4* src = (const float4*)(g_wT + k*4096);
            #pragma unroll
            for (int i = 0; i < 4; i++) {
                int idx = t + 256*i;
                float4 f = src[idx];
                int ci = idx >> 4;
                int c4 = idx & 15;
                float* dst = smf + SM_W + ci*128 + c4*8;
                *(float4*)dst       = make_float4(f.x, f.x, f.y, f.y);
                *(float4*)(dst + 4) = make_float4(f.z, f.z, f.w, f.w);
            }
        }
        // build v[ci][px]: 2-pt vertical lerp (wx == 0); each thread 32 ci of 1 px
        {
            int y0 = smi[SM_Y0 + k*128 + px];
            float wy = smf[SM_WY + k*128 + px];
            int y1 = min(y0+1, 127);
            int x0 = min(max(px + k - 4, 0), 127);
            const float4* A = (const float4*)(xTb + (y0*WW + x0)*CIN + half*32);
            const float4* C = (const float4*)(xTb + (y1*WW + x0)*CIN + half*32);
            float* vcol = smf + SM_V + half*32*128 + px;
            #pragma unroll
            for (int cc = 0; cc < 8; cc++) {
                float4 a = A[cc];
                float4 c = C[cc];
                vcol[(cc*4+0)*128] = a.x + wy*(c.x - a.x);
                vcol[(cc*4+1)*128] = a.y + wy*(c.y - a.y);
                vcol[(cc*4+2)*128] = a.z + wy*(c.z - a.z);
                vcol[(cc*4+3)*128] = a.w + wy*(c.w - a.w);
            }
        }
        __syncthreads();
        // GEMM: acc[c][j] += w_dup[ci][co0+c] * v[ci][p0+2j..2j+1]
        #pragma unroll 2
        for (int ci = 0; ci < 64; ci++) {
            const ulonglong2 w01 = *(const ulonglong2*)(smf + SM_W + ci*128 + co0*2);
            const ulonglong2 w23 = *(const ulonglong2*)(smf + SM_W + ci*128 + co0*2 + 4);
            const ulonglong2 va  = *(const ulonglong2*)(smf + SM_V + ci*128 + p0);
            const ulonglong2 vb  = *(const ulonglong2*)(smf + SM_V + ci*128 + p0 + 4);
            FMA2(acc[0][0], w01.x, va.x, acc[0][0]);
            FMA2(acc[0][1], w01.x, va.y, acc[0][1]);
            FMA2(acc[0][2], w01.x, vb.x, acc[0][2]);
            FMA2(acc[0][3], w01.x, vb.y, acc[0][3]);
            FMA2(acc[1][0], w01.y, va.x, acc[1][0]);
            FMA2(acc[1][1], w01.y, va.y, acc[1][1]);
            FMA2(acc[1][2], w01.y, vb.x, acc[1][2]);
            FMA2(acc[1][3], w01.y, vb.y, acc[1][3]);
            FMA2(acc[2][0], w23.x, va.x, acc[2][0]);
            FMA2(acc[2][1], w23.x, va.y, acc[2][1]);
            FMA2(acc[2][2], w23.x, vb.x, acc[2][2]);
            FMA2(acc[2][3], w23.x, vb.y, acc[2][3]);
            FMA2(acc[3][0], w23.y, va.x, acc[3][0]);
            FMA2(acc[3][1], w23.y, va.y, acc[3][1]);
            FMA2(acc[3][2], w23.y, vb.x, acc[3][2]);
            FMA2(acc[3][3], w23.y, vb.y, acc[3][3]);
        }
    }

    // epilogue: bias, write raw, reduce GN2 partial stats
    float psum = 0.f, psq = 0.f;
    #pragma unroll
    for (int i = 0; i < 4; i++) {
        float bv = b_dsc[co0+i];
        float st[8];
        #pragma unroll
        for (int j = 0; j < 4; j++) {
            float lo, hi;
            UNPACK2(lo, hi, acc[i][j]);
            lo += bv; hi += bv;
            st[2*j] = lo; st[2*j+1] = hi;
            psum += lo + hi;
            psq  += lo*lo + hi*hi;
        }
        float* dst = &g_outraw[((b*COUT + co0+i)*HH + h)*WW + p0];
        *(float4*)dst       = *(float4*)st;
        *(float4*)(dst + 4) = *(float4*)(st + 4);
    }
    smf[SM_RED + t]       = psum;
    smf[SM_RED + 256 + t] = psq;
    __syncthreads();
    if (t < 16) {   // group g == t  (co0>>2 == t&15)
        float sm = 0.f, sq = 0.f;
        #pragma unroll
        for (int j = 0; j < 16; j++) {
            sm += smf[SM_RED + t + 16*j];
            sq += smf[SM_RED + 256 + t + 16*j];
        }
        atomicAdd(&g_stats2[(b*16 + t)*2 + 0], sm);
        atomicAdd(&g_stats2[(b*16 + t)*2 + 1], sq);
    }
}

// ------------- finalize: GN2 + ReLU (float4) -------------
__global__ void finalize_kernel(const float* __restrict__ g_gn,
                                const float* __restrict__ b_gn,
                                float* __restrict__ out) {
    int i4 = blockIdx.x*256 + threadIdx.x;   // 1048576 float4s
    int e  = i4 << 2;
    int b  = e >> 20;
    int co = (e >> 14) & 63;
    int g  = co >> 2;
    float s = g_stats2[(b*16+g)*2+0];
    float q = g_stats2[(b*16+g)*2+1];
    float mean = s * (1.f/65536.f);
    float var  = q * (1.f/65536.f) - mean*mean;
    float inv  = rsqrtf(var + 1e-5f);
    float ga = inv * g_gn[co];
    float be = b_gn[co] - mean*ga;
    float4 v = ((const float4*)g_outraw)[i4];
    v.x = fmaxf(v.x*ga + be, 0.f);
    v.y = fmaxf(v.y*ga + be, 0.f);
    v.z = fmaxf(v.z*ga + be, 0.f);
    v.w = fmaxf(v.w*ga + be, 0.f);
    ((float4*)out)[i4] = v;
}

// ------------- launch -------------
extern "C" void kernel_launch(void* const* d_in, const int* in_sizes, int n_in,
                              void* d_out, int out_size) {
    const float* x        = (const float*)d_in[0];
    const float* w_off    = (const float*)d_in[1];
    const float* b_off    = (const float*)d_in[2];
    const float* g_gn_off = (const float*)d_in[3];
    const float* b_gn_off = (const float*)d_in[4];
    const float* w_dsc    = (const float*)d_in[5];
    const float* b_dsc    = (const float*)d_in[6];
    const float* g_gn     = (const float*)d_in[7];
    const float* b_gn     = (const float*)d_in[8];
    float* out = (float*)d_out;

    cudaFuncSetAttribute(fused_kernel,
                         cudaFuncAttributeMaxDynamicSharedMemorySize,
                         SM_FLOATS*4);

    prep_kernel<<<144, 256>>>(w_dsc);
    conv1_kernel<<<dim3(2,64,4), dim3(64,2)>>>(x, w_off, b_off);
    transpose_kernel<<<dim3(512,2,4), dim3(32,8)>>>(x);
    fused_kernel<<<dim3(128,4), 256, SM_FLOATS*4>>>(g_gn_off, b_gn_off, b_dsc);
    finalize_kernel<<<4096, 256>>>(g_gn, b_gn, out);
}